// round 3
// baseline (speedup 1.0000x reference)
#include <cuda_runtime.h>

// Problem constants (shapes fixed by the reference).
#define NMAX   100000
#define FEAT   64

// ---------------- device scratch (no allocations allowed) ----------------
__device__ float    g_t[NMAX * FEAT];     // transformed features (pre-aggregation)
__device__ float    g_agg[NMAX * FEAT];   // aggregation accumulator
__device__ float    g_h[NMAX * FEAT];     // hidden activations between layers
__device__ unsigned g_degout[NMAX];
__device__ unsigned g_degin[NMAX];
__device__ float    g_iso[NMAX];          // D_out^{-1/2}
__device__ float    g_isi[NMAX];          // D_in^{-1/2}

// Vector float4 global reduction with scalar fallback.
__device__ __forceinline__ void red_add_f32x4(float* p, float4 v) {
#if defined(__CUDA_ARCH__) && (__CUDA_ARCH__ >= 900)
    asm volatile("red.global.add.v4.f32 [%0], {%1,%2,%3,%4};"
                 :: "l"(p), "f"(v.x), "f"(v.y), "f"(v.z), "f"(v.w)
                 : "memory");
#else
    atomicAdd(p + 0, v.x);
    atomicAdd(p + 1, v.y);
    atomicAdd(p + 2, v.z);
    atomicAdd(p + 3, v.w);
#endif
}

// ---------------- kernels ----------------

__global__ void zero_deg_kernel(int nn) {
    int i = blockIdx.x * blockDim.x + threadIdx.x;
    if (i < nn) { g_degout[i] = 0u; g_degin[i] = 0u; }
}

__global__ void deg_kernel(const int* __restrict__ src, const int* __restrict__ dst, int ne) {
    int e = blockIdx.x * blockDim.x + threadIdx.x;
    if (e < ne) {
        atomicAdd(&g_degout[src[e]], 1u);
        atomicAdd(&g_degin[dst[e]], 1u);
    }
}

__global__ void inv_kernel(int nn) {
    int i = blockIdx.x * blockDim.x + threadIdx.x;
    if (i < nn) {
        g_iso[i] = rsqrtf(fmaxf((float)g_degout[i], 1.0f));
        g_isi[i] = rsqrtf(fmaxf((float)g_degin[i], 1.0f));
    }
}

__global__ void zero_agg_kernel(int n4) {
    int i = blockIdx.x * blockDim.x + threadIdx.x;
    if (i < n4) reinterpret_cast<float4*>(g_agg)[i] = make_float4(0.f, 0.f, 0.f, 0.f);
}

// T[node, col] = sum_k (X[node,k] * iso[node]) * W[k, col]
// Tile: 32 nodes x 64 cols per block, 128 threads, each thread 4x4 micro-tile.
// K processed in 64-wide chunks to keep smem small (occupancy-friendly).
template <int K>
__global__ void gemm_kernel(const float* __restrict__ X, const float* __restrict__ W, int nn) {
    constexpr int KC = 64;
    __shared__ float Ws[KC][FEAT];       // weight chunk
    __shared__ float Xs[32][KC + 4];     // +4 float pad: rows land on distinct banks

    const int tid  = threadIdx.x;        // 0..127
    const int tcol = tid & 15;           // 16 column groups of 4
    const int trow = tid >> 4;           // 8 row groups of 4
    const int nodeBase = blockIdx.x * 32;

    float acc[4][4];
#pragma unroll
    for (int i = 0; i < 4; i++)
#pragma unroll
        for (int j = 0; j < 4; j++) acc[i][j] = 0.f;

    for (int k0 = 0; k0 < K; k0 += KC) {
        // load W chunk: KC x 64 floats = 1024 float4
#pragma unroll
        for (int i = tid; i < KC * (FEAT / 4); i += 128) {
            int r = i >> 4, c4 = i & 15;
            *reinterpret_cast<float4*>(&Ws[r][c4 * 4]) =
                *reinterpret_cast<const float4*>(&W[(k0 + r) * FEAT + c4 * 4]);
        }
        // load X chunk (scaled by iso): 32 x KC floats
#pragma unroll
        for (int i = tid; i < 32 * (KC / 4); i += 128) {
            int r = i / (KC / 4), c4 = i % (KC / 4);
            int node = nodeBase + r;
            float4 v = make_float4(0.f, 0.f, 0.f, 0.f);
            if (node < nn) {
                v = *reinterpret_cast<const float4*>(&X[(size_t)node * K + k0 + c4 * 4]);
                float s = g_iso[node];
                v.x *= s; v.y *= s; v.z *= s; v.w *= s;
            }
            *reinterpret_cast<float4*>(&Xs[r][c4 * 4]) = v;
        }
        __syncthreads();

#pragma unroll
        for (int k = 0; k < KC; k++) {
            float4 b4 = *reinterpret_cast<float4*>(&Ws[k][tcol * 4]);
            float a0 = Xs[trow * 4 + 0][k];
            float a1 = Xs[trow * 4 + 1][k];
            float a2 = Xs[trow * 4 + 2][k];
            float a3 = Xs[trow * 4 + 3][k];
            acc[0][0] += a0 * b4.x; acc[0][1] += a0 * b4.y; acc[0][2] += a0 * b4.z; acc[0][3] += a0 * b4.w;
            acc[1][0] += a1 * b4.x; acc[1][1] += a1 * b4.y; acc[1][2] += a1 * b4.z; acc[1][3] += a1 * b4.w;
            acc[2][0] += a2 * b4.x; acc[2][1] += a2 * b4.y; acc[2][2] += a2 * b4.z; acc[2][3] += a2 * b4.w;
            acc[3][0] += a3 * b4.x; acc[3][1] += a3 * b4.y; acc[3][2] += a3 * b4.z; acc[3][3] += a3 * b4.w;
        }
        __syncthreads();
    }

#pragma unroll
    for (int i = 0; i < 4; i++) {
        int node = nodeBase + trow * 4 + i;
        if (node < nn) {
            float4 v = make_float4(acc[i][0], acc[i][1], acc[i][2], acc[i][3]);
            *reinterpret_cast<float4*>(&g_t[(size_t)node * FEAT + tcol * 4]) = v;
        }
    }
}

// agg[dst] += t[src]; 16 threads per edge, one float4 each, vector reduction.
__global__ void scatter_kernel(const int* __restrict__ src, const int* __restrict__ dst, int ne) {
    int idx = blockIdx.x * blockDim.x + threadIdx.x;
    int e = idx >> 4;
    int c = (idx & 15) << 2;
    if (e < ne) {
        int s = __ldg(&src[e]);
        int d = __ldg(&dst[e]);
        float4 v = *reinterpret_cast<const float4*>(&g_t[(size_t)s * FEAT + c]);
        red_add_f32x4(&g_agg[(size_t)d * FEAT + c], v);
    }
}

// out[node, c] = (relu?)(agg[node,c] * isi[node] + b[c])
template <int RELU>
__global__ void finalize_kernel(const float* __restrict__ b, float* __restrict__ out, int nn) {
    int i = blockIdx.x * blockDim.x + threadIdx.x;  // one float4 per thread
    if (i < nn * 16) {
        int node = i >> 4;
        int c = (i & 15) << 2;
        float4 v = *reinterpret_cast<const float4*>(&g_agg[(size_t)i * 4]);
        float s = g_isi[node];
        float4 bb = *reinterpret_cast<const float4*>(&b[c]);
        v.x = v.x * s + bb.x;
        v.y = v.y * s + bb.y;
        v.z = v.z * s + bb.z;
        v.w = v.w * s + bb.w;
        if (RELU) {
            v.x = fmaxf(v.x, 0.f); v.y = fmaxf(v.y, 0.f);
            v.z = fmaxf(v.z, 0.f); v.w = fmaxf(v.w, 0.f);
        }
        *reinterpret_cast<float4*>(&out[(size_t)i * 4]) = v;
    }
}

// ---------------- launch ----------------
extern "C" void kernel_launch(void* const* d_in, const int* in_sizes, int n_in,
                              void* d_out, int out_size) {
    const float* x   = (const float*)d_in[0];
    const int*   src = (const int*)d_in[1];
    const int*   dst = (const int*)d_in[2];
    const float* W1  = (const float*)d_in[3];
    const float* b1  = (const float*)d_in[4];
    const float* W2  = (const float*)d_in[5];
    const float* b2  = (const float*)d_in[6];
    const float* W3  = (const float*)d_in[7];
    const float* b3  = (const float*)d_in[8];
    float* out = (float*)d_out;

    const int nn = in_sizes[0] / 128;   // 100000
    const int ne = in_sizes[1];         // 1600000

    // Cache the symbol address so the captured region contains only launches.
    static float* h_ptr = nullptr;
    if (h_ptr == nullptr) {
        cudaGetSymbolAddress((void**)&h_ptr, g_h);
    }

    const int T = 256;
    const int nodeBlk = (nn + T - 1) / T;
    const int aggBlk  = (nn * 16 + T - 1) / T;
    const int edgeBlk = (ne + T - 1) / T;
    const int scatBlk = (ne * 16 + T - 1) / T;
    const int gemmBlk = (nn + 31) / 32;

    // degrees + normalizers
    zero_deg_kernel<<<nodeBlk, T>>>(nn);
    deg_kernel<<<edgeBlk, T>>>(src, dst, ne);
    inv_kernel<<<nodeBlk, T>>>(nn);

    // ---- layer 1: x(128) -> h(64), relu ----
    gemm_kernel<128><<<gemmBlk, 128>>>(x, W1, nn);
    zero_agg_kernel<<<aggBlk, T>>>(nn * 16);
    scatter_kernel<<<scatBlk, T>>>(src, dst, ne);
    finalize_kernel<1><<<aggBlk, T>>>(b1, h_ptr, nn);

    // ---- layer 2: h(64) -> h(64), relu ----
    gemm_kernel<64><<<gemmBlk, 128>>>(h_ptr, W2, nn);
    zero_agg_kernel<<<aggBlk, T>>>(nn * 16);
    scatter_kernel<<<scatBlk, T>>>(src, dst, ne);
    finalize_kernel<1><<<aggBlk, T>>>(b2, h_ptr, nn);

    // ---- layer 3: h(64) -> out(64), no relu ----
    gemm_kernel<64><<<gemmBlk, 128>>>(h_ptr, W3, nn);
    zero_agg_kernel<<<aggBlk, T>>>(nn * 16);
    scatter_kernel<<<scatBlk, T>>>(src, dst, ne);
    finalize_kernel<0><<<aggBlk, T>>>(b3, out, nn);
}

// round 4
// speedup vs baseline: 1.0027x; 1.0027x over previous
#include <cuda_runtime.h>

// Problem constants (shapes fixed by the reference).
#define NMAX   100000
#define FEAT   64

// ---------------- device scratch (no allocations allowed) ----------------
__device__ float    g_t[NMAX * FEAT];     // transformed features (pre-aggregation)
__device__ float    g_agg[NMAX * FEAT];   // aggregation accumulator
__device__ float    g_h[NMAX * FEAT];     // hidden activations between layers
__device__ unsigned g_degout[NMAX];
__device__ unsigned g_degin[NMAX];
__device__ float    g_iso[NMAX];          // D_out^{-1/2}
__device__ float    g_isi[NMAX];          // D_in^{-1/2}

// Vector float4 global reduction with scalar fallback.
__device__ __forceinline__ void red_add_f32x4(float* p, float4 v) {
#if defined(__CUDA_ARCH__) && (__CUDA_ARCH__ >= 900)
    asm volatile("red.global.add.v4.f32 [%0], {%1,%2,%3,%4};"
                 :: "l"(p), "f"(v.x), "f"(v.y), "f"(v.z), "f"(v.w)
                 : "memory");
#else
    atomicAdd(p + 0, v.x);
    atomicAdd(p + 1, v.y);
    atomicAdd(p + 2, v.z);
    atomicAdd(p + 3, v.w);
#endif
}

// ---------------- kernels ----------------

__global__ void zero_deg_kernel(int nn) {
    int i = blockIdx.x * blockDim.x + threadIdx.x;
    if (i < nn) { g_degout[i] = 0u; g_degin[i] = 0u; }
}

__global__ void deg_kernel(const int* __restrict__ src, const int* __restrict__ dst, int ne) {
    int e = blockIdx.x * blockDim.x + threadIdx.x;
    if (e < ne) {
        atomicAdd(&g_degout[src[e]], 1u);
        atomicAdd(&g_degin[dst[e]], 1u);
    }
}

__global__ void inv_kernel(int nn) {
    int i = blockIdx.x * blockDim.x + threadIdx.x;
    if (i < nn) {
        g_iso[i] = rsqrtf(fmaxf((float)g_degout[i], 1.0f));
        g_isi[i] = rsqrtf(fmaxf((float)g_degin[i], 1.0f));
    }
}

__global__ void zero_agg_kernel(int n4) {
    int i = blockIdx.x * blockDim.x + threadIdx.x;
    if (i < n4) reinterpret_cast<float4*>(g_agg)[i] = make_float4(0.f, 0.f, 0.f, 0.f);
}

// T[node, col] = sum_k (X[node,k] * iso[node]) * W[k, col]
// Tile: 32 nodes x 64 cols per block, 128 threads, each thread 4x4 micro-tile.
// K processed in 64-wide chunks to keep smem small (occupancy-friendly).
template <int K>
__global__ void gemm_kernel(const float* __restrict__ X, const float* __restrict__ W, int nn) {
    constexpr int KC = 64;
    __shared__ float Ws[KC][FEAT];       // weight chunk
    __shared__ float Xs[32][KC + 4];     // +4 float pad: rows land on distinct banks

    const int tid  = threadIdx.x;        // 0..127
    const int tcol = tid & 15;           // 16 column groups of 4
    const int trow = tid >> 4;           // 8 row groups of 4
    const int nodeBase = blockIdx.x * 32;

    float acc[4][4];
#pragma unroll
    for (int i = 0; i < 4; i++)
#pragma unroll
        for (int j = 0; j < 4; j++) acc[i][j] = 0.f;

    for (int k0 = 0; k0 < K; k0 += KC) {
        // load W chunk: KC x 64 floats = 1024 float4
#pragma unroll
        for (int i = tid; i < KC * (FEAT / 4); i += 128) {
            int r = i >> 4, c4 = i & 15;
            *reinterpret_cast<float4*>(&Ws[r][c4 * 4]) =
                *reinterpret_cast<const float4*>(&W[(k0 + r) * FEAT + c4 * 4]);
        }
        // load X chunk (scaled by iso): 32 x KC floats
#pragma unroll
        for (int i = tid; i < 32 * (KC / 4); i += 128) {
            int r = i / (KC / 4), c4 = i % (KC / 4);
            int node = nodeBase + r;
            float4 v = make_float4(0.f, 0.f, 0.f, 0.f);
            if (node < nn) {
                v = *reinterpret_cast<const float4*>(&X[(size_t)node * K + k0 + c4 * 4]);
                float s = g_iso[node];
                v.x *= s; v.y *= s; v.z *= s; v.w *= s;
            }
            *reinterpret_cast<float4*>(&Xs[r][c4 * 4]) = v;
        }
        __syncthreads();

#pragma unroll
        for (int k = 0; k < KC; k++) {
            float4 b4 = *reinterpret_cast<float4*>(&Ws[k][tcol * 4]);
            float a0 = Xs[trow * 4 + 0][k];
            float a1 = Xs[trow * 4 + 1][k];
            float a2 = Xs[trow * 4 + 2][k];
            float a3 = Xs[trow * 4 + 3][k];
            acc[0][0] += a0 * b4.x; acc[0][1] += a0 * b4.y; acc[0][2] += a0 * b4.z; acc[0][3] += a0 * b4.w;
            acc[1][0] += a1 * b4.x; acc[1][1] += a1 * b4.y; acc[1][2] += a1 * b4.z; acc[1][3] += a1 * b4.w;
            acc[2][0] += a2 * b4.x; acc[2][1] += a2 * b4.y; acc[2][2] += a2 * b4.z; acc[2][3] += a2 * b4.w;
            acc[3][0] += a3 * b4.x; acc[3][1] += a3 * b4.y; acc[3][2] += a3 * b4.z; acc[3][3] += a3 * b4.w;
        }
        __syncthreads();
    }

#pragma unroll
    for (int i = 0; i < 4; i++) {
        int node = nodeBase + trow * 4 + i;
        if (node < nn) {
            float4 v = make_float4(acc[i][0], acc[i][1], acc[i][2], acc[i][3]);
            *reinterpret_cast<float4*>(&g_t[(size_t)node * FEAT + tcol * 4]) = v;
        }
    }
}

// agg[dst] += t[src]; 16 threads per edge, one float4 each, vector reduction.
__global__ void scatter_kernel(const int* __restrict__ src, const int* __restrict__ dst, int ne) {
    int idx = blockIdx.x * blockDim.x + threadIdx.x;
    int e = idx >> 4;
    int c = (idx & 15) << 2;
    if (e < ne) {
        int s = __ldg(&src[e]);
        int d = __ldg(&dst[e]);
        float4 v = *reinterpret_cast<const float4*>(&g_t[(size_t)s * FEAT + c]);
        red_add_f32x4(&g_agg[(size_t)d * FEAT + c], v);
    }
}

// out[node, c] = (relu?)(agg[node,c] * isi[node] + b[c])
template <int RELU>
__global__ void finalize_kernel(const float* __restrict__ b, float* __restrict__ out, int nn) {
    int i = blockIdx.x * blockDim.x + threadIdx.x;  // one float4 per thread
    if (i < nn * 16) {
        int node = i >> 4;
        int c = (i & 15) << 2;
        float4 v = *reinterpret_cast<const float4*>(&g_agg[(size_t)i * 4]);
        float s = g_isi[node];
        float4 bb = *reinterpret_cast<const float4*>(&b[c]);
        v.x = v.x * s + bb.x;
        v.y = v.y * s + bb.y;
        v.z = v.z * s + bb.z;
        v.w = v.w * s + bb.w;
        if (RELU) {
            v.x = fmaxf(v.x, 0.f); v.y = fmaxf(v.y, 0.f);
            v.z = fmaxf(v.z, 0.f); v.w = fmaxf(v.w, 0.f);
        }
        *reinterpret_cast<float4*>(&out[(size_t)i * 4]) = v;
    }
}

// ---------------- launch ----------------
extern "C" void kernel_launch(void* const* d_in, const int* in_sizes, int n_in,
                              void* d_out, int out_size) {
    const float* x   = (const float*)d_in[0];
    const int*   src = (const int*)d_in[1];
    const int*   dst = (const int*)d_in[2];
    const float* W1  = (const float*)d_in[3];
    const float* b1  = (const float*)d_in[4];
    const float* W2  = (const float*)d_in[5];
    const float* b2  = (const float*)d_in[6];
    const float* W3  = (const float*)d_in[7];
    const float* b3  = (const float*)d_in[8];
    float* out = (float*)d_out;

    const int nn = in_sizes[0] / 128;   // 100000
    const int ne = in_sizes[1];         // 1600000

    // Cache the symbol address so the captured region contains only launches.
    static float* h_ptr = nullptr;
    if (h_ptr == nullptr) {
        cudaGetSymbolAddress((void**)&h_ptr, g_h);
    }

    const int T = 256;
    const int nodeBlk = (nn + T - 1) / T;
    const int aggBlk  = (nn * 16 + T - 1) / T;
    const int edgeBlk = (ne + T - 1) / T;
    const int scatBlk = (ne * 16 + T - 1) / T;
    const int gemmBlk = (nn + 31) / 32;

    // degrees + normalizers
    zero_deg_kernel<<<nodeBlk, T>>>(nn);
    deg_kernel<<<edgeBlk, T>>>(src, dst, ne);
    inv_kernel<<<nodeBlk, T>>>(nn);

    // ---- layer 1: x(128) -> h(64), relu ----
    gemm_kernel<128><<<gemmBlk, 128>>>(x, W1, nn);
    zero_agg_kernel<<<aggBlk, T>>>(nn * 16);
    scatter_kernel<<<scatBlk, T>>>(src, dst, ne);
    finalize_kernel<1><<<aggBlk, T>>>(b1, h_ptr, nn);

    // ---- layer 2: h(64) -> h(64), relu ----
    gemm_kernel<64><<<gemmBlk, 128>>>(h_ptr, W2, nn);
    zero_agg_kernel<<<aggBlk, T>>>(nn * 16);
    scatter_kernel<<<scatBlk, T>>>(src, dst, ne);
    finalize_kernel<1><<<aggBlk, T>>>(b2, h_ptr, nn);

    // ---- layer 3: h(64) -> out(64), no relu ----
    gemm_kernel<64><<<gemmBlk, 128>>>(h_ptr, W3, nn);
    zero_agg_kernel<<<aggBlk, T>>>(nn * 16);
    scatter_kernel<<<scatBlk, T>>>(src, dst, ne);
    finalize_kernel<0><<<aggBlk, T>>>(b3, out, nn);
}

// round 5
// speedup vs baseline: 1.7303x; 1.7258x over previous
#include <cuda_runtime.h>

// Problem constants (shapes fixed by the reference).
#define NMAX   100000
#define NEMAX  1600000
#define FEAT   64
#define SCAN_T 256
#define SCAN_NB ((NMAX + SCAN_T - 1) / SCAN_T)   // 391

// ---------------- device scratch (no allocations allowed) ----------------
__device__ float    g_t[NMAX * FEAT];     // transformed features (pre-aggregation)
__device__ float    g_h[NMAX * FEAT];     // hidden activations between layers
__device__ unsigned g_degout[NMAX];
__device__ unsigned g_degin[NMAX];
__device__ float    g_iso[NMAX];          // D_out^{-1/2}
__device__ float    g_isi[NMAX];          // D_in^{-1/2}
__device__ int      g_rowstart[NMAX + 1]; // CSR row offsets (by dst)
__device__ int      g_cursor[NMAX];       // fill cursors
__device__ int      g_csr[NEMAX];         // src ids grouped by dst
__device__ int      g_blksum[512];        // scan block totals

// ---------------- degree / normalizer kernels ----------------

__global__ void zero_deg_kernel(int nn) {
    int i = blockIdx.x * blockDim.x + threadIdx.x;
    if (i < nn) { g_degout[i] = 0u; g_degin[i] = 0u; g_cursor[i] = 0; }
    if (i == 0) g_rowstart[0] = 0;
}

__global__ void deg_kernel(const int* __restrict__ src, const int* __restrict__ dst, int ne) {
    int e = blockIdx.x * blockDim.x + threadIdx.x;
    if (e < ne) {
        atomicAdd(&g_degout[src[e]], 1u);
        atomicAdd(&g_degin[dst[e]], 1u);
    }
}

__global__ void inv_kernel(int nn) {
    int i = blockIdx.x * blockDim.x + threadIdx.x;
    if (i < nn) {
        g_iso[i] = rsqrtf(fmaxf((float)g_degout[i], 1.0f));
        g_isi[i] = rsqrtf(fmaxf((float)g_degin[i], 1.0f));
    }
}

// ---------------- prefix-sum (exclusive) over in-degrees -> g_rowstart ----------------
// Pass A: per-block inclusive scan of degin; write to rowstart[i+1], block total to g_blksum.
__global__ void scanA_kernel(int nn) {
    __shared__ int sh[SCAN_T];
    int tid = threadIdx.x;
    int i = blockIdx.x * SCAN_T + tid;
    int v = (i < nn) ? (int)g_degin[i] : 0;
    sh[tid] = v;
    __syncthreads();
#pragma unroll
    for (int off = 1; off < SCAN_T; off <<= 1) {
        int t = (tid >= off) ? sh[tid - off] : 0;
        __syncthreads();
        sh[tid] += t;
        __syncthreads();
    }
    if (i < nn) g_rowstart[i + 1] = sh[tid];
    if (tid == SCAN_T - 1) g_blksum[blockIdx.x] = sh[tid];
}

// Pass B: single block scans the (<=512) block totals in place (inclusive).
__global__ void scanB_kernel(int nb) {
    __shared__ int sh[512];
    int tid = threadIdx.x;
    sh[tid] = (tid < nb) ? g_blksum[tid] : 0;
    __syncthreads();
#pragma unroll
    for (int off = 1; off < 512; off <<= 1) {
        int t = (tid >= off) ? sh[tid - off] : 0;
        __syncthreads();
        sh[tid] += t;
        __syncthreads();
    }
    g_blksum[tid] = sh[tid];
}

// Pass C: add block offsets.
__global__ void scanC_kernel(int nn) {
    int i = blockIdx.x * SCAN_T + threadIdx.x;
    if (i < nn && blockIdx.x > 0) g_rowstart[i + 1] += g_blksum[blockIdx.x - 1];
}

// Fill CSR buckets: int atomics only, one-time cost.
__global__ void csr_fill_kernel(const int* __restrict__ src, const int* __restrict__ dst, int ne) {
    int e = blockIdx.x * blockDim.x + threadIdx.x;
    if (e < ne) {
        int d = dst[e];
        int pos = atomicAdd(&g_cursor[d], 1);
        g_csr[g_rowstart[d] + pos] = src[e];
    }
}

// ---------------- dense transform: T = (X * iso) @ W ----------------
// Tile: 32 nodes x 64 cols per block, 128 threads, each thread 4x4 micro-tile.
template <int K>
__global__ void gemm_kernel(const float* __restrict__ X, const float* __restrict__ W, int nn) {
    constexpr int KC = 64;
    __shared__ float Ws[KC][FEAT];
    __shared__ float Xs[32][KC + 4];

    const int tid  = threadIdx.x;
    const int tcol = tid & 15;
    const int trow = tid >> 4;
    const int nodeBase = blockIdx.x * 32;

    float acc[4][4];
#pragma unroll
    for (int i = 0; i < 4; i++)
#pragma unroll
        for (int j = 0; j < 4; j++) acc[i][j] = 0.f;

    for (int k0 = 0; k0 < K; k0 += KC) {
#pragma unroll
        for (int i = tid; i < KC * (FEAT / 4); i += 128) {
            int r = i >> 4, c4 = i & 15;
            *reinterpret_cast<float4*>(&Ws[r][c4 * 4]) =
                *reinterpret_cast<const float4*>(&W[(k0 + r) * FEAT + c4 * 4]);
        }
#pragma unroll
        for (int i = tid; i < 32 * (KC / 4); i += 128) {
            int r = i / (KC / 4), c4 = i % (KC / 4);
            int node = nodeBase + r;
            float4 v = make_float4(0.f, 0.f, 0.f, 0.f);
            if (node < nn) {
                v = *reinterpret_cast<const float4*>(&X[(size_t)node * K + k0 + c4 * 4]);
                float s = g_iso[node];
                v.x *= s; v.y *= s; v.z *= s; v.w *= s;
            }
            *reinterpret_cast<float4*>(&Xs[r][c4 * 4]) = v;
        }
        __syncthreads();

#pragma unroll
        for (int k = 0; k < KC; k++) {
            float4 b4 = *reinterpret_cast<float4*>(&Ws[k][tcol * 4]);
            float a0 = Xs[trow * 4 + 0][k];
            float a1 = Xs[trow * 4 + 1][k];
            float a2 = Xs[trow * 4 + 2][k];
            float a3 = Xs[trow * 4 + 3][k];
            acc[0][0] += a0 * b4.x; acc[0][1] += a0 * b4.y; acc[0][2] += a0 * b4.z; acc[0][3] += a0 * b4.w;
            acc[1][0] += a1 * b4.x; acc[1][1] += a1 * b4.y; acc[1][2] += a1 * b4.z; acc[1][3] += a1 * b4.w;
            acc[2][0] += a2 * b4.x; acc[2][1] += a2 * b4.y; acc[2][2] += a2 * b4.z; acc[2][3] += a2 * b4.w;
            acc[3][0] += a3 * b4.x; acc[3][1] += a3 * b4.y; acc[3][2] += a3 * b4.z; acc[3][3] += a3 * b4.w;
        }
        __syncthreads();
    }

#pragma unroll
    for (int i = 0; i < 4; i++) {
        int node = nodeBase + trow * 4 + i;
        if (node < nn) {
            float4 v = make_float4(acc[i][0], acc[i][1], acc[i][2], acc[i][3]);
            *reinterpret_cast<float4*>(&g_t[(size_t)node * FEAT + tcol * 4]) = v;
        }
    }
}

// ---------------- CSR gather + finalize: out[n] = relu?(sum_{e in in(n)} t[src_e] * isi[n] + b) ----------------
// 16 lanes per node, each lane owns one float4 column chunk. No atomics, streaming writes.
template <int RELU>
__global__ void gather_kernel(const float* __restrict__ b, float* __restrict__ out, int nn) {
    int idx = blockIdx.x * blockDim.x + threadIdx.x;
    int node = idx >> 4;
    int c = (idx & 15) << 2;
    if (node >= nn) return;

    int rs = g_rowstart[node];
    int re = g_rowstart[node + 1];

    float4 acc = make_float4(0.f, 0.f, 0.f, 0.f);
#pragma unroll 4
    for (int p = rs; p < re; ++p) {
        int s = __ldg(&g_csr[p]);                       // same addr across 16 lanes -> broadcast
        float4 v = __ldg(reinterpret_cast<const float4*>(&g_t[(size_t)s * FEAT + c]));
        acc.x += v.x; acc.y += v.y; acc.z += v.z; acc.w += v.w;
    }

    float sN = g_isi[node];
    float4 bb = *reinterpret_cast<const float4*>(&b[c]);
    acc.x = acc.x * sN + bb.x;
    acc.y = acc.y * sN + bb.y;
    acc.z = acc.z * sN + bb.z;
    acc.w = acc.w * sN + bb.w;
    if (RELU) {
        acc.x = fmaxf(acc.x, 0.f); acc.y = fmaxf(acc.y, 0.f);
        acc.z = fmaxf(acc.z, 0.f); acc.w = fmaxf(acc.w, 0.f);
    }
    *reinterpret_cast<float4*>(&out[(size_t)node * FEAT + c]) = acc;
}

// ---------------- launch ----------------
extern "C" void kernel_launch(void* const* d_in, const int* in_sizes, int n_in,
                              void* d_out, int out_size) {
    const float* x   = (const float*)d_in[0];
    const int*   src = (const int*)d_in[1];
    const int*   dst = (const int*)d_in[2];
    const float* W1  = (const float*)d_in[3];
    const float* b1  = (const float*)d_in[4];
    const float* W2  = (const float*)d_in[5];
    const float* b2  = (const float*)d_in[6];
    const float* W3  = (const float*)d_in[7];
    const float* b3  = (const float*)d_in[8];
    float* out = (float*)d_out;

    const int nn = in_sizes[0] / 128;   // 100000
    const int ne = in_sizes[1];         // 1600000

    static float* h_ptr = nullptr;
    if (h_ptr == nullptr) {
        cudaGetSymbolAddress((void**)&h_ptr, g_h);
    }

    const int T = 256;
    const int nodeBlk = (nn + T - 1) / T;
    const int edgeBlk = (ne + T - 1) / T;
    const int gathBlk = (nn * 16 + T - 1) / T;
    const int gemmBlk = (nn + 31) / 32;
    const int scanNB  = (nn + SCAN_T - 1) / SCAN_T;

    // ---- one-time graph preprocessing: degrees, normalizers, dst-CSR ----
    zero_deg_kernel<<<nodeBlk, T>>>(nn);
    deg_kernel<<<edgeBlk, T>>>(src, dst, ne);
    inv_kernel<<<nodeBlk, T>>>(nn);
    scanA_kernel<<<scanNB, SCAN_T>>>(nn);
    scanB_kernel<<<1, 512>>>(scanNB);
    scanC_kernel<<<scanNB, SCAN_T>>>(nn);
    csr_fill_kernel<<<edgeBlk, T>>>(src, dst, ne);

    // ---- layer 1: x(128) -> h(64), relu ----
    gemm_kernel<128><<<gemmBlk, 128>>>(x, W1, nn);
    gather_kernel<1><<<gathBlk, T>>>(b1, h_ptr, nn);

    // ---- layer 2: h(64) -> h(64), relu ----
    gemm_kernel<64><<<gemmBlk, 128>>>(h_ptr, W2, nn);
    gather_kernel<1><<<gathBlk, T>>>(b2, h_ptr, nn);

    // ---- layer 3: h(64) -> out(64), no relu ----
    gemm_kernel<64><<<gemmBlk, 128>>>(h_ptr, W3, nn);
    gather_kernel<0><<<gathBlk, T>>>(b3, out, nn);
}

// round 7
// speedup vs baseline: 1.8407x; 1.0638x over previous
#include <cuda_runtime.h>
#include <mma.h>

using namespace nvcuda;

// Problem constants (shapes fixed by the reference).
#define NMAX   100000
#define NEMAX  1600000
#define FEAT   64
#define SCAN_T 256

// ---------------- device scratch (no allocations allowed) ----------------
// g_t padded by 128 rows: last GEMM block stores a full 128-row tile unguarded.
__device__ float    g_t[(NMAX + 128) * FEAT];
__device__ float    g_h[NMAX * FEAT];
__device__ unsigned g_degout[NMAX];
__device__ unsigned g_degin[NMAX];
__device__ float    g_iso[NMAX];          // D_out^{-1/2}
__device__ float    g_isi[NMAX];          // D_in^{-1/2}
__device__ int      g_rowstart[NMAX + 1]; // CSR row offsets (by dst)
__device__ int      g_cursor[NMAX];       // fill cursors
__device__ int      g_csr[NEMAX];         // src ids grouped by dst
__device__ int      g_blksum[512];        // scan block totals

// ---------------- degree / normalizer kernels ----------------

__global__ void zero_deg_kernel(int nn) {
    int i = blockIdx.x * blockDim.x + threadIdx.x;
    if (i < nn) { g_degout[i] = 0u; g_degin[i] = 0u; g_cursor[i] = 0; }
    if (i == 0) g_rowstart[0] = 0;
}

__global__ void deg_kernel(const int* __restrict__ src, const int* __restrict__ dst, int ne) {
    int e = blockIdx.x * blockDim.x + threadIdx.x;
    if (e < ne) {
        atomicAdd(&g_degout[src[e]], 1u);
        atomicAdd(&g_degin[dst[e]], 1u);
    }
}

__global__ void inv_kernel(int nn) {
    int i = blockIdx.x * blockDim.x + threadIdx.x;
    if (i < nn) {
        g_iso[i] = rsqrtf(fmaxf((float)g_degout[i], 1.0f));
        g_isi[i] = rsqrtf(fmaxf((float)g_degin[i], 1.0f));
    }
}

// ---------------- prefix-sum (exclusive) over in-degrees -> g_rowstart ----------------
__global__ void scanA_kernel(int nn) {
    __shared__ int sh[SCAN_T];
    int tid = threadIdx.x;
    int i = blockIdx.x * SCAN_T + tid;
    int v = (i < nn) ? (int)g_degin[i] : 0;
    sh[tid] = v;
    __syncthreads();
#pragma unroll
    for (int off = 1; off < SCAN_T; off <<= 1) {
        int t = (tid >= off) ? sh[tid - off] : 0;
        __syncthreads();
        sh[tid] += t;
        __syncthreads();
    }
    if (i < nn) g_rowstart[i + 1] = sh[tid];
    if (tid == SCAN_T - 1) g_blksum[blockIdx.x] = sh[tid];
}

__global__ void scanB_kernel(int nb) {
    __shared__ int sh[512];
    int tid = threadIdx.x;
    sh[tid] = (tid < nb) ? g_blksum[tid] : 0;
    __syncthreads();
#pragma unroll
    for (int off = 1; off < 512; off <<= 1) {
        int t = (tid >= off) ? sh[tid - off] : 0;
        __syncthreads();
        sh[tid] += t;
        __syncthreads();
    }
    g_blksum[tid] = sh[tid];
}

__global__ void scanC_kernel(int nn) {
    int i = blockIdx.x * SCAN_T + threadIdx.x;
    if (i < nn && blockIdx.x > 0) g_rowstart[i + 1] += g_blksum[blockIdx.x - 1];
}

__global__ void csr_fill_kernel(const int* __restrict__ src, const int* __restrict__ dst, int ne) {
    int e = blockIdx.x * blockDim.x + threadIdx.x;
    if (e < ne) {
        int d = dst[e];
        int pos = atomicAdd(&g_cursor[d], 1);
        g_csr[g_rowstart[d] + pos] = src[e];
    }
}

// ---------------- dense transform via TF32 tensor cores ----------------
// T = (X * iso) @ W. Block tile: 128 nodes x 64 cols, 256 threads (8 warps),
// each warp a 32x32 subtile = 2x2 wmma m16n16k8 fragments. K chunked at 32
// for BOTH X and W (keeps static smem at 27.1 KB, under the 48 KB limit).
template <int K>
__global__ void gemm_mma_kernel(const float* __restrict__ X, const float* __restrict__ W, int nn) {
    constexpr int KC  = 32;
    constexpr int XLD = KC + 4;       // 36 floats; multiple of 4 for wmma ldm
    constexpr int WLD = FEAT + 4;     // 68 floats

    __shared__ float Ws[KC][WLD];     // weight K-chunk
    __shared__ float Xs[128][XLD];    // node-feature K-chunk (iso-scaled)

    const int tid = threadIdx.x;
    const int wid = tid >> 5;
    const int warp_row = wid >> 1;    // 0..3 -> 32-row band
    const int warp_col = wid & 1;     // 0..1 -> 32-col band
    const int nodeBase = blockIdx.x * 128;

    wmma::fragment<wmma::accumulator, 16, 16, 8, float> acc[2][2];
#pragma unroll
    for (int r = 0; r < 2; r++)
#pragma unroll
        for (int c = 0; c < 2; c++) wmma::fill_fragment(acc[r][c], 0.0f);

    for (int k0 = 0; k0 < K; k0 += KC) {
        // Load W chunk: KC x 64 floats.
#pragma unroll
        for (int i = tid; i < KC * (FEAT / 4); i += 256) {
            int r = i >> 4, c4 = i & 15;
            float4 v = *reinterpret_cast<const float4*>(&W[(k0 + r) * FEAT + c4 * 4]);
            *reinterpret_cast<float4*>(&Ws[r][c4 * 4]) = v;
        }
        // Load X chunk, scaled by iso; zero-fill rows beyond nn.
#pragma unroll
        for (int i = tid; i < 128 * (KC / 4); i += 256) {
            int r = i / (KC / 4), c4 = i % (KC / 4);
            int node = nodeBase + r;
            float4 v = make_float4(0.f, 0.f, 0.f, 0.f);
            if (node < nn) {
                v = *reinterpret_cast<const float4*>(&X[(size_t)node * K + k0 + c4 * 4]);
                float s = g_iso[node];
                v.x *= s; v.y *= s; v.z *= s; v.w *= s;
            }
            *reinterpret_cast<float4*>(&Xs[r][c4 * 4]) = v;
        }
        __syncthreads();

#pragma unroll
        for (int kk = 0; kk < KC; kk += 8) {
            wmma::fragment<wmma::matrix_a, 16, 16, 8, wmma::precision::tf32, wmma::row_major> a[2];
            wmma::fragment<wmma::matrix_b, 16, 16, 8, wmma::precision::tf32, wmma::row_major> b[2];
#pragma unroll
            for (int r = 0; r < 2; r++) {
                wmma::load_matrix_sync(a[r], &Xs[warp_row * 32 + r * 16][kk], XLD);
#pragma unroll
                for (int t = 0; t < a[r].num_elements; t++)
                    a[r].x[t] = wmma::__float_to_tf32(a[r].x[t]);
            }
#pragma unroll
            for (int c = 0; c < 2; c++) {
                wmma::load_matrix_sync(b[c], &Ws[kk][warp_col * 32 + c * 16], WLD);
#pragma unroll
                for (int t = 0; t < b[c].num_elements; t++)
                    b[c].x[t] = wmma::__float_to_tf32(b[c].x[t]);
            }
#pragma unroll
            for (int r = 0; r < 2; r++)
#pragma unroll
                for (int c = 0; c < 2; c++)
                    wmma::mma_sync(acc[r][c], a[r], b[c], acc[r][c]);
        }
        __syncthreads();
    }

    // Store 32x32 per warp into g_t (padded, so unguarded stores are safe).
#pragma unroll
    for (int r = 0; r < 2; r++)
#pragma unroll
        for (int c = 0; c < 2; c++) {
            int row = nodeBase + warp_row * 32 + r * 16;
            int col = warp_col * 32 + c * 16;
            wmma::store_matrix_sync(&g_t[(size_t)row * FEAT + col], acc[r][c], FEAT,
                                    wmma::mem_row_major);
        }
}

// ---------------- CSR gather + finalize ----------------
// 16 lanes per node, each lane owns one float4 column chunk. No atomics.
template <int RELU>
__global__ void gather_kernel(const float* __restrict__ b, float* __restrict__ out, int nn) {
    int idx = blockIdx.x * blockDim.x + threadIdx.x;
    int node = idx >> 4;
    int c = (idx & 15) << 2;
    if (node >= nn) return;

    int rs = g_rowstart[node];
    int re = g_rowstart[node + 1];

    float4 acc = make_float4(0.f, 0.f, 0.f, 0.f);
#pragma unroll 4
    for (int p = rs; p < re; ++p) {
        int s = __ldg(&g_csr[p]);
        float4 v = __ldg(reinterpret_cast<const float4*>(&g_t[(size_t)s * FEAT + c]));
        acc.x += v.x; acc.y += v.y; acc.z += v.z; acc.w += v.w;
    }

    float sN = g_isi[node];
    float4 bb = *reinterpret_cast<const float4*>(&b[c]);
    acc.x = acc.x * sN + bb.x;
    acc.y = acc.y * sN + bb.y;
    acc.z = acc.z * sN + bb.z;
    acc.w = acc.w * sN + bb.w;
    if (RELU) {
        acc.x = fmaxf(acc.x, 0.f); acc.y = fmaxf(acc.y, 0.f);
        acc.z = fmaxf(acc.z, 0.f); acc.w = fmaxf(acc.w, 0.f);
    }
    *reinterpret_cast<float4*>(&out[(size_t)node * FEAT + c]) = acc;
}

// ---------------- launch ----------------
extern "C" void kernel_launch(void* const* d_in, const int* in_sizes, int n_in,
                              void* d_out, int out_size) {
    const float* x   = (const float*)d_in[0];
    const int*   src = (const int*)d_in[1];
    const int*   dst = (const int*)d_in[2];
    const float* W1  = (const float*)d_in[3];
    const float* b1  = (const float*)d_in[4];
    const float* W2  = (const float*)d_in[5];
    const float* b2  = (const float*)d_in[6];
    const float* W3  = (const float*)d_in[7];
    const float* b3  = (const float*)d_in[8];
    float* out = (float*)d_out;

    const int nn = in_sizes[0] / 128;   // 100000
    const int ne = in_sizes[1];         // 1600000

    static float* h_ptr = nullptr;
    if (h_ptr == nullptr) {
        cudaGetSymbolAddress((void**)&h_ptr, g_h);
    }

    const int T = 256;
    const int nodeBlk = (nn + T - 1) / T;
    const int edgeBlk = (ne + T - 1) / T;
    const int gathBlk = (nn * 16 + T - 1) / T;
    const int gemmBlk = (nn + 127) / 128;
    const int scanNB  = (nn + SCAN_T - 1) / SCAN_T;

    // ---- one-time graph preprocessing: degrees, normalizers, dst-CSR ----
    zero_deg_kernel<<<nodeBlk, T>>>(nn);
    deg_kernel<<<edgeBlk, T>>>(src, dst, ne);
    inv_kernel<<<nodeBlk, T>>>(nn);
    scanA_kernel<<<scanNB, SCAN_T>>>(nn);
    scanB_kernel<<<1, 512>>>(scanNB);
    scanC_kernel<<<scanNB, SCAN_T>>>(nn);
    csr_fill_kernel<<<edgeBlk, T>>>(src, dst, ne);

    // ---- layer 1: x(128) -> h(64), relu ----
    gemm_mma_kernel<128><<<gemmBlk, 256>>>(x, W1, nn);
    gather_kernel<1><<<gathBlk, T>>>(b1, h_ptr, nn);

    // ---- layer 2: h(64) -> h(64), relu ----
    gemm_mma_kernel<64><<<gemmBlk, 256>>>(h_ptr, W2, nn);
    gather_kernel<1><<<gathBlk, T>>>(b2, h_ptr, nn);

    // ---- layer 3: h(64) -> out(64), no relu ----
    gemm_mma_kernel<64><<<gemmBlk, 256>>>(h_ptr, W3, nn);
    gather_kernel<0><<<gathBlk, T>>>(b3, out, nn);
}